// round 13
// baseline (speedup 1.0000x reference)
#include <cuda_runtime.h>
#include <math.h>

#define NV 1024
#define NM 8192
#define DEG 8
#define SD 64
#define HD 128
#define NSTEPS 10

typedef unsigned long long u64;

__device__ __forceinline__ u64 pk2(float lo, float hi) {
    u64 r; asm("mov.b64 %0,{%1,%2};" : "=l"(r) : "f"(lo), "f"(hi)); return r;
}
__device__ __forceinline__ void up2(u64 v, float& lo, float& hi) {
    asm("mov.b64 {%0,%1},%2;" : "=f"(lo), "=f"(hi) : "l"(v));
}
__device__ __forceinline__ void fma2(u64& d, u64 a, u64 b) {
    asm("fma.rn.f32x2 %0,%1,%2,%0;" : "+l"(d) : "l"(a), "l"(b));
}

// ---------------- persistent device state ----------------
__device__ float g_hv[NM*SD];     // h_v2f
__device__ float g_hf[NM*SD];     // h_f2v
__device__ int   g_varlist[NV*DEG];
// pre-transposed weights (smem-layout-exact, filled once by k_prep)
__device__ float g_W1Tv[129*128];
__device__ float g_W2Tv[128*128];
__device__ float g_W1Tf[130*128];
__device__ float g_W2Tf[128*128];
__device__ float g_WhhV[192*65];
__device__ float g_WhhF[192*65];

__device__ __forceinline__ float sigm(float x) {
    return __fdividef(1.f, 1.f + __expf(-x));
}
__device__ __forceinline__ float tanh_fast(float x) {
    return 1.f - __fdividef(2.f, __expf(2.f*x) + 1.f);
}

// ---------------- init ----------------
__global__ void k_init_a() {
    int idx = blockIdx.x*blockDim.x + threadIdx.x;
    if (idx < NM*SD) { g_hv[idx] = 0.f; g_hf[idx] = 0.f; }
}
// single block: build varlist (order-free via atomics, then sorted -> deterministic)
__global__ void __launch_bounds__(1024) k_init_bc(const int* __restrict__ node_var) {
    __shared__ int scnt[NV];
    int t = threadIdx.x;
    scnt[t] = 0;
    __syncthreads();
    for (int m = t; m < NM; m += 1024) {
        int u = node_var[m];
        int pos = atomicAdd(&scnt[u], 1);
        g_varlist[u*DEG + pos] = m;
    }
    __syncthreads();
    int* p = &g_varlist[t*DEG];
    for (int a = 1; a < DEG; a++) {
        int key = p[a]; int b = a - 1;
        while (b >= 0 && p[b] > key) { p[b+1] = p[b]; b--; }
        p[b+1] = key;
    }
}
// one-time weight pre-transposition
__global__ void k_prep(const float* __restrict__ W1v, const float* __restrict__ W2v,
                       const float* __restrict__ W1f, const float* __restrict__ W2f,
                       const float* __restrict__ WhhV, const float* __restrict__ WhhF)
{
    int i = blockIdx.x*blockDim.x + threadIdx.x;
    if (i < 16512) { int c = i / 129, k = i - c*129; g_W1Tv[k*128 + c] = W1v[i]; }
    if (i < 16384) { int c = i >> 7,  k = i & 127;  g_W2Tv[k*128 + c] = W2v[i]; }
    if (i < 16640) { int c = i / 130, k = i - c*130; g_W1Tf[k*128 + c] = W1f[i]; }
    if (i < 16384) { int c = i >> 7,  k = i & 127;  g_W2Tf[k*128 + c] = W2f[i]; }
    if (i < 12288) { int q = i >> 6,  k = i & 63;   g_WhhV[q*65 + k] = WhhV[i];
                                                    g_WhhF[q*65 + k] = WhhF[i]; }
    if (i < 192)   { g_WhhV[i*65 + 64] = 0.f; g_WhhF[i*65 + 64] = 0.f; }
}

// ---------------- K2F: fused P/Q + edge MLP + segsum + GRU(h_v2f) -------
// smem floats:
//  sW    0     .. 16512   (W1T [129][128] -> W2T [128][128] -> GRU weights)
//  shfT  16512 .. 17280   ([64 k][12] nodes 0..7)
//  shvT  17280 .. 18048
//  sbv   18048 .. 18056
//  sP    18056 .. 19080   ([8][128])
//  sQ    19080 .. 20104
//  l1T   20104 .. 27272   ([128 col][56 edge])
//  sPart 27272 .. 27528
//  snm   27528 .. 27544
#define K2_SMEM (27544*4)
__global__ void __launch_bounds__(256) k2_edges(
    const float* __restrict__ b1v, const float* __restrict__ b2v,
    const float* __restrict__ W3, const float* __restrict__ b3,
    const float* __restrict__ gWih,
    const float* __restrict__ gbih, const float* __restrict__ gbhh,
    const float* __restrict__ bvec)
{
    extern __shared__ float sm[];
    __shared__ int smIdx[8];
    float* sW    = sm;
    float* shfT  = sm + 16512;
    float* shvT  = sm + 17280;
    float* sbv   = sm + 18048;
    float* sP    = sm + 18056;
    float* sQ    = sm + 19080;
    float* l1T   = sm + 20104;
    float* sPart = sm + 27272;
    float* snm   = sm + 27528;
    int t = threadIdx.x, v = blockIdx.x;
    int wid = t >> 5, lane = t & 31;
    if (t < 8) smIdx[t] = g_varlist[v*DEG + t];
    // stage W1T (float4, conflict-free)
    for (int i4 = t; i4 < 4128; i4 += 256)
        ((float4*)sW)[i4] = ((const float4*)g_W1Tv)[i4];
    __syncthreads();   // smIdx + W1T visible
    // stage h tiles transposed [k][n] pitch 12 (single trip: t<256 -> n 0..3, +4 covers 4..7)
    {
        int n = t >> 6, k = t & 63;
        shfT[k*12 + n]     = g_hf[smIdx[n]*SD + k];
        shfT[k*12 + n + 4] = g_hf[smIdx[n+4]*SD + k];
        shvT[k*12 + n]     = g_hv[smIdx[n]*SD + k];
        shvT[k*12 + n + 4] = g_hv[smIdx[n+4]*SD + k];
    }
    if (t < 8) sbv[t] = bvec[v];   // node_var of every msg-node in this block == v
    __syncthreads();
    // ---- P/Q compute: 8 warp tasks (pq, quad, colhalf)
    {
        int pq = wid >> 2, quad = (wid >> 1) & 1, ch = wid & 1;
        int nq = quad*4, c0 = ch*64 + lane*2;
        const float* hT = pq ? shvT : shfT;
        float* dstS = pq ? sQ : sP;
        int kofs = pq ? 64 : 0;
        u64 a0a, a0b, a1a, a1b;
        if (pq) {
            float wl0 = sW[128*128 + c0], wl1 = sW[128*128 + c0 + 1];
            float rb0 = b1v[c0], rb1_ = b1v[c0+1];
            float bA = sbv[nq], bB = sbv[nq+1], bC = sbv[nq+2], bD = sbv[nq+3];
            a0a = pk2(fmaf(bA, wl0, rb0),  fmaf(bB, wl0, rb0));
            a0b = pk2(fmaf(bC, wl0, rb0),  fmaf(bD, wl0, rb0));
            a1a = pk2(fmaf(bA, wl1, rb1_), fmaf(bB, wl1, rb1_));
            a1b = pk2(fmaf(bC, wl1, rb1_), fmaf(bD, wl1, rb1_));
        } else { a0a = a0b = a1a = a1b = 0ULL; }
        #pragma unroll 8
        for (int k = 0; k < 64; k++) {
            ulonglong2 h2 = *(const ulonglong2*)&hT[k*12 + nq];
            u64 w01 = *(const u64*)&sW[(k + kofs)*128 + c0];
            float w0, w1; up2(w01, w0, w1);
            u64 w00 = pk2(w0, w0), w11 = pk2(w1, w1);
            fma2(a0a, h2.x, w00); fma2(a0b, h2.y, w00);
            fma2(a1a, h2.x, w11); fma2(a1b, h2.y, w11);
        }
        float A0, B0, C0, D0, A1, B1, C1, D1;
        up2(a0a, A0, B0); up2(a0b, C0, D0);
        up2(a1a, A1, B1); up2(a1b, C1, D1);
        *(float2*)&dstS[(nq+0)*HD + c0] = make_float2(A0, A1);
        *(float2*)&dstS[(nq+1)*HD + c0] = make_float2(B0, B1);
        *(float2*)&dstS[(nq+2)*HD + c0] = make_float2(C0, C1);
        *(float2*)&dstS[(nq+3)*HD + c0] = make_float2(D0, D1);
    }
    __syncthreads();
    // ---- l1 combine (reads sP/sQ)
    {
        int col = t & 127, e0 = (t >> 7) * 4;
        #pragma unroll
        for (int g = 0; g < 7; g++) {
            int be = g*8 + e0;
            float l1v[4];
            #pragma unroll
            for (int q = 0; q < 4; q++) {
                int e = be + q, ii = e/7, jj = e - ii*7;
                int j = jj + (jj >= ii);
                l1v[q] = fmaxf(sP[j*HD + col] + sQ[ii*HD + col], 0.f);
            }
            *(float4*)&l1T[col*56 + be] = make_float4(l1v[0], l1v[1], l1v[2], l1v[3]);
        }
    }
    __syncthreads();
    // stage W2T over dead W1T region
    for (int i4 = t; i4 < 4096; i4 += 256)
        ((float4*)sW)[i4] = ((const float4*)g_W2Tv)[i4];
    __syncthreads();
    // ---- layer2+layer3: warp tasks (g, colhalf), 2 passes
    #pragma unroll
    for (int pass = 0; pass < 2; pass++) {
        int tt = pass*8 + wid;
        if (tt < 14) {
            int g = tt % 7, ch = tt / 7;
            int c0 = ch*64 + lane*2;
            float rb0 = b2v[c0], rb1_ = b2v[c0+1];
            u64 acc[2][4];
            #pragma unroll
            for (int ep = 0; ep < 4; ep++) { acc[0][ep] = pk2(rb0, rb0); acc[1][ep] = pk2(rb1_, rb1_); }
            const float* l1base = l1T + g*8;
            #pragma unroll 8
            for (int k = 0; k < 128; k++) {
                ulonglong2 Ea = *(const ulonglong2*)&l1base[k*56];
                ulonglong2 Eb = *(const ulonglong2*)&l1base[k*56 + 4];
                u64 w01 = *(const u64*)&sW[k*128 + c0];
                float w0, w1; up2(w01, w0, w1);
                u64 w00 = pk2(w0, w0), w11 = pk2(w1, w1);
                fma2(acc[0][0], Ea.x, w00); fma2(acc[0][1], Ea.y, w00);
                fma2(acc[0][2], Eb.x, w00); fma2(acc[0][3], Eb.y, w00);
                fma2(acc[1][0], Ea.x, w11); fma2(acc[1][1], Ea.y, w11);
                fma2(acc[1][2], Eb.x, w11); fma2(acc[1][3], Eb.y, w11);
            }
            float w30a = W3[c0], w30b = W3[c0+1];
            float w31a = W3[HD+c0], w31b = W3[HD+c0+1];
            #pragma unroll
            for (int ep = 0; ep < 4; ep++) {
                float lA0, lB0, lA1, lB1;
                up2(acc[0][ep], lA0, lB0);
                up2(acc[1][ep], lA1, lB1);
                lA0 = fmaxf(lA0, 0.f); lB0 = fmaxf(lB0, 0.f);
                lA1 = fmaxf(lA1, 0.f); lB1 = fmaxf(lB1, 0.f);
                float pA0 = fmaf(lA1, w30b, lA0*w30a);
                float pA1 = fmaf(lA1, w31b, lA0*w31a);
                float pB0 = fmaf(lB1, w30b, lB0*w30a);
                float pB1 = fmaf(lB1, w31b, lB0*w31a);
                #pragma unroll
                for (int off = 16; off; off >>= 1) {
                    pA0 += __shfl_xor_sync(0xffffffffu, pA0, off);
                    pA1 += __shfl_xor_sync(0xffffffffu, pA1, off);
                    pB0 += __shfl_xor_sync(0xffffffffu, pB0, off);
                    pB1 += __shfl_xor_sync(0xffffffffu, pB1, off);
                }
                if (lane == 0) {
                    int baseI = g*32 + ch*16;
                    sPart[baseI + (2*ep)*2 + 0] = pA0;
                    sPart[baseI + (2*ep)*2 + 1] = pA1;
                    sPart[baseI + (2*ep+1)*2 + 0] = pB0;
                    sPart[baseI + (2*ep+1)*2 + 1] = pB1;
                }
            }
        }
    }
    __syncthreads();
    // ---- deterministic segment-sum
    if (t < 16) {
        int ii = t >> 1, c = t & 1;
        float s = 0.f;
        #pragma unroll
        for (int jj = 0; jj < 7; jj++) {
            int e = ii*7 + jj;
            int g = e >> 3, slot = e & 7;
            s += sPart[g*32 + slot*2 + c] + sPart[g*32 + 16 + slot*2 + c];
        }
        snm[ii*2 + c] = s;
    }
    // GRU weights overlay sW (dead after layer2); h_v2f comes from live shvT
    float* sWhh = sm;            // [192][65]
    float* sWih = sm + 12480;    // 384
    float* sbih = sm + 12864;    // 192
    float* sbhh = sm + 13056;    // 192
    for (int i4 = t; i4 < 3120; i4 += 256)
        ((float4*)sWhh)[i4] = ((const float4*)g_WhhV)[i4];
    for (int i4 = t; i4 < 96; i4 += 256) ((float4*)sWih)[i4] = ((const float4*)gWih)[i4];
    if (t < 192) { sbih[t] = gbih[t]; sbhh[t] = gbhh[t]; }
    __syncthreads();
    float sb30 = 7.f*b3[0], sb31 = 7.f*b3[1];
    int nn = t >> 5, s0 = t & 31;
    float x0 = snm[nn*2] + sb30, x1 = snm[nn*2+1] + sb31;
    #pragma unroll
    for (int j2 = 0; j2 < 2; j2++) {
        int s = s0 + j2*32;
        float gir = fmaf(x1, sWih[2*s+1],       fmaf(x0, sWih[2*s],       sbih[s]));
        float giz = fmaf(x1, sWih[2*(64+s)+1],  fmaf(x0, sWih[2*(64+s)],  sbih[64+s]));
        float gin = fmaf(x1, sWih[2*(128+s)+1], fmaf(x0, sWih[2*(128+s)], sbih[128+s]));
        float ghr = sbhh[s], ghz = sbhh[64+s], ghn = sbhh[128+s];
        const float* wr = sWhh + s*65;
        const float* wz = sWhh + (64+s)*65;
        const float* wg = sWhh + (128+s)*65;
        #pragma unroll 8
        for (int k = 0; k < 64; k++) {
            float h = shvT[k*12 + nn];
            ghr = fmaf(h, wr[k], ghr);
            ghz = fmaf(h, wz[k], ghz);
            ghn = fmaf(h, wg[k], ghn);
        }
        float r  = sigm(gir + ghr);
        float z  = sigm(giz + ghz);
        float gg = tanh_fast(fmaf(r, ghn, gin));
        float h  = shvT[s*12 + nn];
        g_hv[smIdx[nn]*SD + s] = fmaf(z, h - gg, gg);
    }
}

// ---------------- K3: f2v MLP + logsumexp + GRU(h_f2v) ----------------
// smem floats: sW 16640 | sXT 4680 | l1T 4608 | sAB 64 | sEm 64 | sNew 64 | sPart 128 = 26248
#define K3_SMEM (26248*4)
__global__ void __launch_bounds__(256) k3_f2v(
    const float* __restrict__ Jm, const float* __restrict__ b1v,
    const float* __restrict__ b2v,
    const float* __restrict__ W3, const float* __restrict__ b3,
    const float* __restrict__ gWih,
    const float* __restrict__ gbih, const float* __restrict__ gbhh,
    const float* __restrict__ bvec, const int* __restrict__ node_var)
{
    extern __shared__ float sm[];
    float* sW    = sm;           // W1T/W2T pitch 128 -> GRU weights
    float* sXT   = sm + 16640;   // [k 0..129][n 0..31] pitch 36
    float* l1T   = sm + 21320;   // [col 0..127][n 0..31] pitch 36
    float* sAB   = sm + 25928;
    float* sEm   = sm + 25992;
    float* sNew  = sm + 26056;
    float* sPart = sm + 26120;   // [ch][n 0..31][2]
    int t = threadIdx.x;
    int mb = blockIdx.x * 32;
    int wid = t >> 5, lane = t & 31;
    for (int i4 = t; i4 < 4160; i4 += 256)
        ((float4*)sW)[i4] = ((const float4*)g_W1Tf)[i4];
    for (int i = t; i < 2048; i += 256) {
        int n = i >> 6, k = i & 63;
        sXT[k*36 + n]        = g_hv[(mb+n)*SD + k];
        sXT[(64+k)*36 + n]   = g_hf[(mb + (n^1))*SD + k];
    }
    if (t < 32) {
        int u = node_var[mb + t], vv = node_var[mb + (t^1)];
        sXT[128*36 + t] = bvec[u];
        sXT[129*36 + t] = bvec[vv];
        sAB[t*2]   = Jm[u*NV + vv];
        sAB[t*2+1] = Jm[vv*NV + u];
    }
    __syncthreads();
    // ---- layer1: 8 warp tasks (nodechunk, colhalf)
    {
        int nc = (wid & 3) * 8, ch = wid >> 2;
        int c0 = ch*64 + lane*2;
        float rb0 = b1v[c0], rb1_ = b1v[c0+1];
        u64 acc[2][4];
        #pragma unroll
        for (int np = 0; np < 4; np++) { acc[0][np] = pk2(rb0, rb0); acc[1][np] = pk2(rb1_, rb1_); }
        #pragma unroll 8
        for (int k = 0; k < 130; k++) {
            ulonglong2 Xa = *(const ulonglong2*)&sXT[k*36 + nc];
            ulonglong2 Xb = *(const ulonglong2*)&sXT[k*36 + nc + 4];
            u64 w01 = *(const u64*)&sW[k*128 + c0];
            float w0, w1; up2(w01, w0, w1);
            u64 w00 = pk2(w0, w0), w11 = pk2(w1, w1);
            fma2(acc[0][0], Xa.x, w00); fma2(acc[0][1], Xa.y, w00);
            fma2(acc[0][2], Xb.x, w00); fma2(acc[0][3], Xb.y, w00);
            fma2(acc[1][0], Xa.x, w11); fma2(acc[1][1], Xa.y, w11);
            fma2(acc[1][2], Xb.x, w11); fma2(acc[1][3], Xb.y, w11);
        }
        #pragma unroll
        for (int c = 0; c < 2; c++) {
            float v[8];
            #pragma unroll
            for (int np = 0; np < 4; np++) up2(acc[c][np], v[2*np], v[2*np+1]);
            #pragma unroll
            for (int j = 0; j < 8; j++) v[j] = fmaxf(v[j], 0.f);
            *(float4*)&l1T[(c0+c)*36 + nc]     = make_float4(v[0], v[1], v[2], v[3]);
            *(float4*)&l1T[(c0+c)*36 + nc + 4] = make_float4(v[4], v[5], v[6], v[7]);
        }
    }
    __syncthreads();
    for (int i4 = t; i4 < 4096; i4 += 256)
        ((float4*)sW)[i4] = ((const float4*)g_W2Tf)[i4];
    __syncthreads();
    // ---- layer2 + layer3
    {
        int nc = (wid & 3) * 8, ch = wid >> 2;
        int c0 = ch*64 + lane*2;
        float rb0 = b2v[c0], rb1_ = b2v[c0+1];
        u64 acc[2][4];
        #pragma unroll
        for (int np = 0; np < 4; np++) { acc[0][np] = pk2(rb0, rb0); acc[1][np] = pk2(rb1_, rb1_); }
        #pragma unroll 8
        for (int k = 0; k < 128; k++) {
            ulonglong2 La = *(const ulonglong2*)&l1T[k*36 + nc];
            ulonglong2 Lb = *(const ulonglong2*)&l1T[k*36 + nc + 4];
            u64 w01 = *(const u64*)&sW[k*128 + c0];
            float w0, w1; up2(w01, w0, w1);
            u64 w00 = pk2(w0, w0), w11 = pk2(w1, w1);
            fma2(acc[0][0], La.x, w00); fma2(acc[0][1], La.y, w00);
            fma2(acc[0][2], Lb.x, w00); fma2(acc[0][3], Lb.y, w00);
            fma2(acc[1][0], La.x, w11); fma2(acc[1][1], La.y, w11);
            fma2(acc[1][2], Lb.x, w11); fma2(acc[1][3], Lb.y, w11);
        }
        float w30a = W3[c0], w30b = W3[c0+1];
        float w31a = W3[HD+c0], w31b = W3[HD+c0+1];
        #pragma unroll
        for (int np = 0; np < 4; np++) {
            float lA0, lB0, lA1, lB1;
            up2(acc[0][np], lA0, lB0);
            up2(acc[1][np], lA1, lB1);
            lA0 = fmaxf(lA0, 0.f); lB0 = fmaxf(lB0, 0.f);
            lA1 = fmaxf(lA1, 0.f); lB1 = fmaxf(lB1, 0.f);
            float pA0 = fmaf(lA1, w30b, lA0*w30a);
            float pA1 = fmaf(lA1, w31b, lA0*w31a);
            float pB0 = fmaf(lB1, w30b, lB0*w30a);
            float pB1 = fmaf(lB1, w31b, lB0*w31a);
            #pragma unroll
            for (int off = 16; off; off >>= 1) {
                pA0 += __shfl_xor_sync(0xffffffffu, pA0, off);
                pA1 += __shfl_xor_sync(0xffffffffu, pA1, off);
                pB0 += __shfl_xor_sync(0xffffffffu, pB0, off);
                pB1 += __shfl_xor_sync(0xffffffffu, pB1, off);
            }
            if (lane == 0) {
                int nA = nc + 2*np, nB = nA + 1;
                sPart[ch*64 + nA*2 + 0] = pA0;
                sPart[ch*64 + nA*2 + 1] = pA1;
                sPart[ch*64 + nB*2 + 0] = pB0;
                sPart[ch*64 + nB*2 + 1] = pB1;
            }
        }
    }
    __syncthreads();
    if (t < 64) {
        int n = t >> 1, c = t & 1;
        sEm[n*2 + c] = sPart[n*2 + c] + sPart[64 + n*2 + c] + b3[c];
    }
    __syncthreads();
    // per-node logsumexp over 2x2 factor table
    if (t < 64) {
        int n = t >> 1, c = t & 1;
        float A = sAB[n*2], B = sAB[n*2+1];
        float em0 = sEm[n*2], em1 = sEm[n*2+1];
        float a = (c == 0) ? (A + B + em0) : (-2.f*A + em0);
        float d = (c == 0) ? (-2.f*B + em1) : (A + B + em1);
        float mx = fmaxf(a, d), mn = fminf(a, d);
        sNew[n*2 + c] = mx + log1pf(expf(mn - mx));
    }
    __syncthreads();
    // GRU(h_f2v), x = new[sib]; weights overlay sW
    float* sWih = sW + 12480; float* sbih = sW + 12864; float* sbhh = sW + 13056;
    for (int i4 = t; i4 < 3120; i4 += 256)
        ((float4*)sW)[i4] = ((const float4*)g_WhhF)[i4];
    for (int i4 = t; i4 < 96; i4 += 256) ((float4*)sWih)[i4] = ((const float4*)gWih)[i4];
    if (t < 192) { sbih[t] = gbih[t]; sbhh[t] = gbhh[t]; }
    __syncthreads();
    int nn = t >> 3, s0b = t & 7, sibl = nn ^ 1;
    float x0 = sNew[sibl*2], x1 = sNew[sibl*2 + 1];
    #pragma unroll
    for (int j2 = 0; j2 < 8; j2++) {
        int s = s0b + j2*8;
        float gir = fmaf(x1, sWih[2*s+1],       fmaf(x0, sWih[2*s],       sbih[s]));
        float giz = fmaf(x1, sWih[2*(64+s)+1],  fmaf(x0, sWih[2*(64+s)],  sbih[64+s]));
        float gin = fmaf(x1, sWih[2*(128+s)+1], fmaf(x0, sWih[2*(128+s)], sbih[128+s]));
        float ghr = sbhh[s], ghz = sbhh[64+s], ghn = sbhh[128+s];
        const float* wr = sW + s*65;
        const float* wz = sW + (64+s)*65;
        const float* wg = sW + (128+s)*65;
        #pragma unroll 8
        for (int k = 0; k < 64; k++) {
            float h = sXT[(64+k)*36 + sibl];   // == h_f2v[mb+nn][k]
            ghr = fmaf(h, wr[k], ghr);
            ghz = fmaf(h, wz[k], ghz);
            ghn = fmaf(h, wg[k], ghn);
        }
        float r  = sigm(gir + ghr);
        float z  = sigm(giz + ghz);
        float gg = tanh_fast(fmaf(r, ghn, gin));
        float h  = sXT[(64+s)*36 + sibl];
        g_hf[(mb+nn)*SD + s] = fmaf(z, h - gg, gg);
    }
}

// ---------------- K4: readout MLP + softmax ----------------
// smem floats: sW1 8256 | sW2 16512 | snm 64 | sh1 128 | sh2 128 | sp 8 = 25096
#define K4_SMEM (25096*4)
__global__ void __launch_bounds__(128) k4_readout(
    const float* __restrict__ W1, const float* __restrict__ b1,
    const float* __restrict__ W2, const float* __restrict__ b2,
    const float* __restrict__ W3, const float* __restrict__ b3,
    float* __restrict__ out)
{
    extern __shared__ float sm[];
    float* sW1 = sm;
    float* sW2 = sm + 8256;
    float* snm = sm + 24768;
    float* sh1 = sm + 24832;
    float* sh2 = sm + 24960;
    float* sp  = sm + 25088;
    int t = threadIdx.x, v = blockIdx.x;
    for (int i = t; i < 8192; i += 128)  { int c = i >> 6, k = i & 63;  sW1[k*129+c] = W1[i]; }
    for (int i = t; i < 16384; i += 128) { int c = i >> 7, k = i & 127; sW2[k*129+c] = W2[i]; }
    if (t < 64) {
        float s = 0.f;
        #pragma unroll
        for (int d = 0; d < 8; d++) s += g_hf[g_varlist[v*DEG + d]*SD + t];
        snm[t] = s;
    }
    __syncthreads();
    {
        float acc = b1[t];
        #pragma unroll 8
        for (int k = 0; k < 64; k++) acc = fmaf(snm[k], sW1[k*129 + t], acc);
        sh1[t] = fmaxf(acc, 0.f);
    }
    __syncthreads();
    {
        float acc = b2[t];
        #pragma unroll 8
        for (int k = 0; k < 128; k++) acc = fmaf(sh1[k], sW2[k*129 + t], acc);
        sh2[t] = fmaxf(acc, 0.f);
    }
    __syncthreads();
    float h2 = sh2[t];
    float p0 = h2 * W3[t], p1 = h2 * W3[128 + t];
    #pragma unroll
    for (int off = 16; off; off >>= 1) {
        p0 += __shfl_xor_sync(0xffffffffu, p0, off);
        p1 += __shfl_xor_sync(0xffffffffu, p1, off);
    }
    int wid = t >> 5;
    if ((t & 31) == 0) { sp[wid*2] = p0; sp[wid*2+1] = p1; }
    __syncthreads();
    if (t == 0) {
        float l0 = sp[0] + sp[2] + sp[4] + sp[6] + b3[0];
        float l1 = sp[1] + sp[3] + sp[5] + sp[7] + b3[1];
        float m = fmaxf(l0, l1);
        float e0 = expf(l0 - m), e1 = expf(l1 - m);
        float inv = 1.f / (e0 + e1);
        out[v*2]     = e0 * inv;
        out[v*2 + 1] = e1 * inv;
    }
}

// ---------------- launch ----------------
extern "C" void kernel_launch(void* const* d_in, const int* in_sizes, int n_in,
                              void* d_out, int out_size) {
    (void)in_sizes; (void)n_in; (void)out_size;
    const float* J        = (const float*)d_in[0];
    const float* b        = (const float*)d_in[1];
    const int*   node_var = (const int*)  d_in[2];
    // d_in[3], d_in[4] (e1_row, e1_col) intentionally unused (structure rebuilt on device)
    const float* v2f_W1 = (const float*)d_in[5];
    const float* v2f_b1 = (const float*)d_in[6];
    const float* v2f_W2 = (const float*)d_in[7];
    const float* v2f_b2 = (const float*)d_in[8];
    const float* v2f_W3 = (const float*)d_in[9];
    const float* v2f_b3 = (const float*)d_in[10];
    const float* f2v_W1 = (const float*)d_in[11];
    const float* f2v_b1 = (const float*)d_in[12];
    const float* f2v_W2 = (const float*)d_in[13];
    const float* f2v_b2 = (const float*)d_in[14];
    const float* f2v_W3 = (const float*)d_in[15];
    const float* f2v_b3 = (const float*)d_in[16];
    const float* gv_Wih = (const float*)d_in[17];
    const float* gv_Whh = (const float*)d_in[18];
    const float* gv_bih = (const float*)d_in[19];
    const float* gv_bhh = (const float*)d_in[20];
    const float* gf_Wih = (const float*)d_in[21];
    const float* gf_Whh = (const float*)d_in[22];
    const float* gf_bih = (const float*)d_in[23];
    const float* gf_bhh = (const float*)d_in[24];
    const float* ro_W1  = (const float*)d_in[25];
    const float* ro_b1  = (const float*)d_in[26];
    const float* ro_W2  = (const float*)d_in[27];
    const float* ro_b2  = (const float*)d_in[28];
    const float* ro_W3  = (const float*)d_in[29];
    const float* ro_b3  = (const float*)d_in[30];

    cudaFuncSetAttribute((const void*)k2_edges,   cudaFuncAttributeMaxDynamicSharedMemorySize, K2_SMEM);
    cudaFuncSetAttribute((const void*)k3_f2v,     cudaFuncAttributeMaxDynamicSharedMemorySize, K3_SMEM);
    cudaFuncSetAttribute((const void*)k4_readout, cudaFuncAttributeMaxDynamicSharedMemorySize, K4_SMEM);

    k_init_a<<<2048, 256>>>();
    k_init_bc<<<1, 1024>>>(node_var);
    k_prep<<<65, 256>>>(v2f_W1, v2f_W2, f2v_W1, f2v_W2, gv_Whh, gf_Whh);
    for (int s = 0; s < NSTEPS; s++) {
        k2_edges<<<NV, 256, K2_SMEM>>>(v2f_b1, v2f_b2, v2f_W3, v2f_b3,
                                       gv_Wih, gv_bih, gv_bhh, b);
        k3_f2v<<<NM/32, 256, K3_SMEM>>>(J, f2v_b1, f2v_b2, f2v_W3, f2v_b3,
                                        gf_Wih, gf_bih, gf_bhh, b, node_var);
    }
    k4_readout<<<NV, 128, K4_SMEM>>>(ro_W1, ro_b1, ro_W2, ro_b2, ro_W3, ro_b3, (float*)d_out);
}

// round 14
// speedup vs baseline: 1.0821x; 1.0821x over previous
#include <cuda_runtime.h>
#include <math.h>

#define NV 1024
#define NM 8192
#define DEG 8
#define SD 64
#define HD 128
#define NSTEPS 10

typedef unsigned long long u64;

__device__ __forceinline__ u64 pk2(float lo, float hi) {
    u64 r; asm("mov.b64 %0,{%1,%2};" : "=l"(r) : "f"(lo), "f"(hi)); return r;
}
__device__ __forceinline__ void up2(u64 v, float& lo, float& hi) {
    asm("mov.b64 {%0,%1},%2;" : "=f"(lo), "=f"(hi) : "l"(v));
}
__device__ __forceinline__ void fma2(u64& d, u64 a, u64 b) {
    asm("fma.rn.f32x2 %0,%1,%2,%0;" : "+l"(d) : "l"(a), "l"(b));
}

// ---------------- persistent device state ----------------
__device__ float g_hv[NM*SD];     // h_v2f
__device__ float g_hf[NM*SD];     // h_f2v
__device__ int   g_varlist[NV*DEG];
// pre-transposed weights (smem-layout-exact, filled once by k_prep)
__device__ float g_W1Tv[129*128];
__device__ float g_W2Tv[128*128];
__device__ float g_W1Tf[130*128];
__device__ float g_W2Tf[128*128];
__device__ float g_WhhV[192*65];
__device__ float g_WhhF[192*65];

__device__ __forceinline__ float sigm(float x) {
    return __fdividef(1.f, 1.f + __expf(-x));
}
__device__ __forceinline__ float tanh_fast(float x) {
    return 1.f - __fdividef(2.f, __expf(2.f*x) + 1.f);
}

// ---------------- init ----------------
__global__ void k_init_a() {
    int idx = blockIdx.x*blockDim.x + threadIdx.x;
    if (idx < NM*SD) { g_hv[idx] = 0.f; g_hf[idx] = 0.f; }
}
// single block: build varlist (order-free via atomics, then sorted -> deterministic)
__global__ void __launch_bounds__(1024) k_init_bc(const int* __restrict__ node_var) {
    __shared__ int scnt[NV];
    int t = threadIdx.x;
    scnt[t] = 0;
    __syncthreads();
    for (int m = t; m < NM; m += 1024) {
        int u = node_var[m];
        int pos = atomicAdd(&scnt[u], 1);
        g_varlist[u*DEG + pos] = m;
    }
    __syncthreads();
    int* p = &g_varlist[t*DEG];
    for (int a = 1; a < DEG; a++) {
        int key = p[a]; int b = a - 1;
        while (b >= 0 && p[b] > key) { p[b+1] = p[b]; b--; }
        p[b+1] = key;
    }
}
// one-time weight pre-transposition
__global__ void k_prep(const float* __restrict__ W1v, const float* __restrict__ W2v,
                       const float* __restrict__ W1f, const float* __restrict__ W2f,
                       const float* __restrict__ WhhV, const float* __restrict__ WhhF)
{
    int i = blockIdx.x*blockDim.x + threadIdx.x;
    if (i < 16512) { int c = i / 129, k = i - c*129; g_W1Tv[k*128 + c] = W1v[i]; }
    if (i < 16384) { int c = i >> 7,  k = i & 127;  g_W2Tv[k*128 + c] = W2v[i]; }
    if (i < 16640) { int c = i / 130, k = i - c*130; g_W1Tf[k*128 + c] = W1f[i]; }
    if (i < 16384) { int c = i >> 7,  k = i & 127;  g_W2Tf[k*128 + c] = W2f[i]; }
    if (i < 12288) { int q = i >> 6,  k = i & 63;   g_WhhV[q*65 + k] = WhhV[i];
                                                    g_WhhF[q*65 + k] = WhhF[i]; }
    if (i < 192)   { g_WhhV[i*65 + 64] = 0.f; g_WhhF[i*65 + 64] = 0.f; }
}

// ---------------- K2F: fused P/Q + edge MLP + segsum + GRU(h_v2f) -------
// smem floats:
//  sW    0     .. 16512   (W1T [129][128] -> W2T [128][128] -> GRU weights)
//  shfT  16512 .. 17280   ([64 k][12] nodes 0..7)
//  shvT  17280 .. 18048
//  sbv   18048 .. 18056
//  sP    18056 .. 19080   ([8][128])
//  sQ    19080 .. 20104
//  l1T   20104 .. 27272   ([128 col][56 edge])
//  sPart 27272 .. 27528   ([7 g][8 e][2])
//  snm   27528 .. 27544
#define K2_SMEM (27544*4)
__global__ void __launch_bounds__(256) k2_edges(
    const float* __restrict__ b1v, const float* __restrict__ b2v,
    const float* __restrict__ W3, const float* __restrict__ b3,
    const float* __restrict__ gWih,
    const float* __restrict__ gbih, const float* __restrict__ gbhh,
    const float* __restrict__ bvec)
{
    extern __shared__ float sm[];
    __shared__ int smIdx[8];
    float* sW    = sm;
    float* shfT  = sm + 16512;
    float* shvT  = sm + 17280;
    float* sbv   = sm + 18048;
    float* sP    = sm + 18056;
    float* sQ    = sm + 19080;
    float* l1T   = sm + 20104;
    float* sPart = sm + 27272;
    float* snm   = sm + 27528;
    int t = threadIdx.x, v = blockIdx.x;
    int wid = t >> 5, lane = t & 31;
    // ---- Phase A: stage W1T + h tiles + sbv + smIdx (all independent)
    if (t < 8) smIdx[t] = g_varlist[v*DEG + t];
    for (int i4 = t; i4 < 4128; i4 += 256)
        ((float4*)sW)[i4] = ((const float4*)g_W1Tv)[i4];
    {
        int n = t >> 6, k = t & 63;
        int iA = g_varlist[v*DEG + n], iB = g_varlist[v*DEG + n + 4];
        shfT[k*12 + n]     = g_hf[iA*SD + k];
        shfT[k*12 + n + 4] = g_hf[iB*SD + k];
        shvT[k*12 + n]     = g_hv[iA*SD + k];
        shvT[k*12 + n + 4] = g_hv[iB*SD + k];
    }
    if (t < 8) sbv[t] = bvec[v];   // node_var of every msg-node in this block == v
    __syncthreads();
    // ---- P/Q compute: 8 warp tasks (pq, quad, colhalf)
    {
        int pq = wid >> 2, quad = (wid >> 1) & 1, ch = wid & 1;
        int nq = quad*4, c0 = ch*64 + lane*2;
        const float* hT = pq ? shvT : shfT;
        float* dstS = pq ? sQ : sP;
        int kofs = pq ? 64 : 0;
        u64 a0a, a0b, a1a, a1b;
        if (pq) {
            float wl0 = sW[128*128 + c0], wl1 = sW[128*128 + c0 + 1];
            float rb0 = b1v[c0], rb1_ = b1v[c0+1];
            float bA = sbv[nq], bB = sbv[nq+1], bC = sbv[nq+2], bD = sbv[nq+3];
            a0a = pk2(fmaf(bA, wl0, rb0),  fmaf(bB, wl0, rb0));
            a0b = pk2(fmaf(bC, wl0, rb0),  fmaf(bD, wl0, rb0));
            a1a = pk2(fmaf(bA, wl1, rb1_), fmaf(bB, wl1, rb1_));
            a1b = pk2(fmaf(bC, wl1, rb1_), fmaf(bD, wl1, rb1_));
        } else { a0a = a0b = a1a = a1b = 0ULL; }
        #pragma unroll 8
        for (int k = 0; k < 64; k++) {
            ulonglong2 h2 = *(const ulonglong2*)&hT[k*12 + nq];
            u64 w01 = *(const u64*)&sW[(k + kofs)*128 + c0];
            float w0, w1; up2(w01, w0, w1);
            u64 w00 = pk2(w0, w0), w11 = pk2(w1, w1);
            fma2(a0a, h2.x, w00); fma2(a0b, h2.y, w00);
            fma2(a1a, h2.x, w11); fma2(a1b, h2.y, w11);
        }
        float A0, B0, C0, D0, A1, B1, C1, D1;
        up2(a0a, A0, B0); up2(a0b, C0, D0);
        up2(a1a, A1, B1); up2(a1b, C1, D1);
        *(float2*)&dstS[(nq+0)*HD + c0] = make_float2(A0, A1);
        *(float2*)&dstS[(nq+1)*HD + c0] = make_float2(B0, B1);
        *(float2*)&dstS[(nq+2)*HD + c0] = make_float2(C0, C1);
        *(float2*)&dstS[(nq+3)*HD + c0] = make_float2(D0, D1);
    }
    __syncthreads();
    // ---- l1 combine (reads sP/sQ) + stage W2T over dead W1T region (merged phase)
    {
        int col = t & 127, e0 = (t >> 7) * 4;
        #pragma unroll
        for (int g = 0; g < 7; g++) {
            int be = g*8 + e0;
            float l1v[4];
            #pragma unroll
            for (int q = 0; q < 4; q++) {
                int e = be + q, ii = e/7, jj = e - ii*7;
                int j = jj + (jj >= ii);
                l1v[q] = fmaxf(sP[j*HD + col] + sQ[ii*HD + col], 0.f);
            }
            *(float4*)&l1T[col*56 + be] = make_float4(l1v[0], l1v[1], l1v[2], l1v[3]);
        }
    }
    for (int i4 = t; i4 < 4096; i4 += 256)
        ((float4*)sW)[i4] = ((const float4*)g_W2Tv)[i4];
    __syncthreads();
    // ---- layer2+layer3: 7 warp tasks (one edge-group each), 4 cols/lane
    if (wid < 7) {
        int g = wid;
        int c0 = lane*4;
        float rb[4];
        *(float4*)rb = *(const float4*)&b2v[c0];
        u64 acc[4][4];
        #pragma unroll
        for (int cp = 0; cp < 4; cp++)
            #pragma unroll
            for (int ep = 0; ep < 4; ep++)
                acc[cp][ep] = pk2(rb[cp], rb[cp]);
        const float* l1base = l1T + g*8;
        #pragma unroll 4
        for (int k = 0; k < 128; k++) {
            ulonglong2 Ea = *(const ulonglong2*)&l1base[k*56];       // edges 0..3
            ulonglong2 Eb = *(const ulonglong2*)&l1base[k*56 + 4];   // edges 4..7
            float4 w4 = *(const float4*)&sW[k*128 + c0];
            u64 ws0 = pk2(w4.x, w4.x), ws1 = pk2(w4.y, w4.y);
            u64 ws2 = pk2(w4.z, w4.z), ws3 = pk2(w4.w, w4.w);
            fma2(acc[0][0], Ea.x, ws0); fma2(acc[0][1], Ea.y, ws0);
            fma2(acc[0][2], Eb.x, ws0); fma2(acc[0][3], Eb.y, ws0);
            fma2(acc[1][0], Ea.x, ws1); fma2(acc[1][1], Ea.y, ws1);
            fma2(acc[1][2], Eb.x, ws1); fma2(acc[1][3], Eb.y, ws1);
            fma2(acc[2][0], Ea.x, ws2); fma2(acc[2][1], Ea.y, ws2);
            fma2(acc[2][2], Eb.x, ws2); fma2(acc[2][3], Eb.y, ws2);
            fma2(acc[3][0], Ea.x, ws3); fma2(acc[3][1], Ea.y, ws3);
            fma2(acc[3][2], Eb.x, ws3); fma2(acc[3][3], Eb.y, ws3);
        }
        // layer3 partials: p{0,1}[e] over this lane's 4 cols, then shfl tree
        float w30v[4], w31v[4];
        *(float4*)w30v = *(const float4*)&W3[c0];
        *(float4*)w31v = *(const float4*)&W3[HD + c0];
        float p0[8], p1[8];
        #pragma unroll
        for (int e = 0; e < 8; e++) { p0[e] = 0.f; p1[e] = 0.f; }
        #pragma unroll
        for (int cp = 0; cp < 4; cp++) {
            #pragma unroll
            for (int ep = 0; ep < 4; ep++) {
                float lo, hi; up2(acc[cp][ep], lo, hi);
                lo = fmaxf(lo, 0.f); hi = fmaxf(hi, 0.f);
                p0[2*ep]   = fmaf(lo, w30v[cp], p0[2*ep]);
                p1[2*ep]   = fmaf(lo, w31v[cp], p1[2*ep]);
                p0[2*ep+1] = fmaf(hi, w30v[cp], p0[2*ep+1]);
                p1[2*ep+1] = fmaf(hi, w31v[cp], p1[2*ep+1]);
            }
        }
        #pragma unroll
        for (int e = 0; e < 8; e++) {
            #pragma unroll
            for (int off = 16; off; off >>= 1) {
                p0[e] += __shfl_xor_sync(0xffffffffu, p0[e], off);
                p1[e] += __shfl_xor_sync(0xffffffffu, p1[e], off);
            }
            if (lane == 0) {
                sPart[g*16 + e*2]     = p0[e];
                sPart[g*16 + e*2 + 1] = p1[e];
            }
        }
    }
    __syncthreads();
    // ---- deterministic segment-sum
    if (t < 16) {
        int ii = t >> 1, c = t & 1;
        float s = 0.f;
        #pragma unroll
        for (int jj = 0; jj < 7; jj++) {
            int e = ii*7 + jj;
            int g = e >> 3, slot = e & 7;
            s += sPart[g*16 + slot*2 + c];
        }
        snm[ii*2 + c] = s;
    }
    // GRU weights overlay sW (dead after layer2); h_v2f comes from live shvT
    float* sWhh = sm;            // [192][65]
    float* sWih = sm + 12480;    // 384
    float* sbih = sm + 12864;    // 192
    float* sbhh = sm + 13056;    // 192
    for (int i4 = t; i4 < 3120; i4 += 256)
        ((float4*)sWhh)[i4] = ((const float4*)g_WhhV)[i4];
    for (int i4 = t; i4 < 96; i4 += 256) ((float4*)sWih)[i4] = ((const float4*)gWih)[i4];
    if (t < 192) { sbih[t] = gbih[t]; sbhh[t] = gbhh[t]; }
    __syncthreads();
    float sb30 = 7.f*b3[0], sb31 = 7.f*b3[1];
    int nn = t >> 5, s0 = t & 31;
    float x0 = snm[nn*2] + sb30, x1 = snm[nn*2+1] + sb31;
    #pragma unroll
    for (int j2 = 0; j2 < 2; j2++) {
        int s = s0 + j2*32;
        float gir = fmaf(x1, sWih[2*s+1],       fmaf(x0, sWih[2*s],       sbih[s]));
        float giz = fmaf(x1, sWih[2*(64+s)+1],  fmaf(x0, sWih[2*(64+s)],  sbih[64+s]));
        float gin = fmaf(x1, sWih[2*(128+s)+1], fmaf(x0, sWih[2*(128+s)], sbih[128+s]));
        float ghr = sbhh[s], ghz = sbhh[64+s], ghn = sbhh[128+s];
        const float* wr = sWhh + s*65;
        const float* wz = sWhh + (64+s)*65;
        const float* wg = sWhh + (128+s)*65;
        #pragma unroll 8
        for (int k = 0; k < 64; k++) {
            float h = shvT[k*12 + nn];
            ghr = fmaf(h, wr[k], ghr);
            ghz = fmaf(h, wz[k], ghz);
            ghn = fmaf(h, wg[k], ghn);
        }
        float r  = sigm(gir + ghr);
        float z  = sigm(giz + ghz);
        float gg = tanh_fast(fmaf(r, ghn, gin));
        float h  = shvT[s*12 + nn];
        g_hv[smIdx[nn]*SD + s] = fmaf(z, h - gg, gg);
    }
}

// ---------------- K3: f2v MLP + logsumexp + GRU(h_f2v) ----------------
// smem floats: sW 16640 | sXT 4680 | l1T 4608 | sAB 64 | sEm 64 | sNew 64 | sPart 128 = 26248
#define K3_SMEM (26248*4)
__global__ void __launch_bounds__(256) k3_f2v(
    const float* __restrict__ Jm, const float* __restrict__ b1v,
    const float* __restrict__ b2v,
    const float* __restrict__ W3, const float* __restrict__ b3,
    const float* __restrict__ gWih,
    const float* __restrict__ gbih, const float* __restrict__ gbhh,
    const float* __restrict__ bvec, const int* __restrict__ node_var)
{
    extern __shared__ float sm[];
    float* sW    = sm;           // W1T/W2T pitch 128 -> GRU weights
    float* sXT   = sm + 16640;   // [k 0..129][n 0..31] pitch 36
    float* l1T   = sm + 21320;   // [col 0..127][n 0..31] pitch 36
    float* sAB   = sm + 25928;
    float* sEm   = sm + 25992;
    float* sNew  = sm + 26056;
    float* sPart = sm + 26120;   // [ch][n 0..31][2]
    int t = threadIdx.x;
    int mb = blockIdx.x * 32;
    int wid = t >> 5, lane = t & 31;
    for (int i4 = t; i4 < 4160; i4 += 256)
        ((float4*)sW)[i4] = ((const float4*)g_W1Tf)[i4];
    for (int i = t; i < 2048; i += 256) {
        int n = i >> 6, k = i & 63;
        sXT[k*36 + n]        = g_hv[(mb+n)*SD + k];
        sXT[(64+k)*36 + n]   = g_hf[(mb + (n^1))*SD + k];
    }
    if (t < 32) {
        int u = node_var[mb + t], vv = node_var[mb + (t^1)];
        sXT[128*36 + t] = bvec[u];
        sXT[129*36 + t] = bvec[vv];
        sAB[t*2]   = Jm[u*NV + vv];
        sAB[t*2+1] = Jm[vv*NV + u];
    }
    __syncthreads();
    // ---- layer1: 8 warp tasks (nodechunk, colhalf)
    {
        int nc = (wid & 3) * 8, ch = wid >> 2;
        int c0 = ch*64 + lane*2;
        float rb0 = b1v[c0], rb1_ = b1v[c0+1];
        u64 acc[2][4];
        #pragma unroll
        for (int np = 0; np < 4; np++) { acc[0][np] = pk2(rb0, rb0); acc[1][np] = pk2(rb1_, rb1_); }
        #pragma unroll 8
        for (int k = 0; k < 130; k++) {
            ulonglong2 Xa = *(const ulonglong2*)&sXT[k*36 + nc];
            ulonglong2 Xb = *(const ulonglong2*)&sXT[k*36 + nc + 4];
            u64 w01 = *(const u64*)&sW[k*128 + c0];
            float w0, w1; up2(w01, w0, w1);
            u64 w00 = pk2(w0, w0), w11 = pk2(w1, w1);
            fma2(acc[0][0], Xa.x, w00); fma2(acc[0][1], Xa.y, w00);
            fma2(acc[0][2], Xb.x, w00); fma2(acc[0][3], Xb.y, w00);
            fma2(acc[1][0], Xa.x, w11); fma2(acc[1][1], Xa.y, w11);
            fma2(acc[1][2], Xb.x, w11); fma2(acc[1][3], Xb.y, w11);
        }
        #pragma unroll
        for (int c = 0; c < 2; c++) {
            float v[8];
            #pragma unroll
            for (int np = 0; np < 4; np++) up2(acc[c][np], v[2*np], v[2*np+1]);
            #pragma unroll
            for (int j = 0; j < 8; j++) v[j] = fmaxf(v[j], 0.f);
            *(float4*)&l1T[(c0+c)*36 + nc]     = make_float4(v[0], v[1], v[2], v[3]);
            *(float4*)&l1T[(c0+c)*36 + nc + 4] = make_float4(v[4], v[5], v[6], v[7]);
        }
    }
    __syncthreads();
    for (int i4 = t; i4 < 4096; i4 += 256)
        ((float4*)sW)[i4] = ((const float4*)g_W2Tf)[i4];
    __syncthreads();
    // ---- layer2 + layer3
    {
        int nc = (wid & 3) * 8, ch = wid >> 2;
        int c0 = ch*64 + lane*2;
        float rb0 = b2v[c0], rb1_ = b2v[c0+1];
        u64 acc[2][4];
        #pragma unroll
        for (int np = 0; np < 4; np++) { acc[0][np] = pk2(rb0, rb0); acc[1][np] = pk2(rb1_, rb1_); }
        #pragma unroll 8
        for (int k = 0; k < 128; k++) {
            ulonglong2 La = *(const ulonglong2*)&l1T[k*36 + nc];
            ulonglong2 Lb = *(const ulonglong2*)&l1T[k*36 + nc + 4];
            u64 w01 = *(const u64*)&sW[k*128 + c0];
            float w0, w1; up2(w01, w0, w1);
            u64 w00 = pk2(w0, w0), w11 = pk2(w1, w1);
            fma2(acc[0][0], La.x, w00); fma2(acc[0][1], La.y, w00);
            fma2(acc[0][2], Lb.x, w00); fma2(acc[0][3], Lb.y, w00);
            fma2(acc[1][0], La.x, w11); fma2(acc[1][1], La.y, w11);
            fma2(acc[1][2], Lb.x, w11); fma2(acc[1][3], Lb.y, w11);
        }
        float w30a = W3[c0], w30b = W3[c0+1];
        float w31a = W3[HD+c0], w31b = W3[HD+c0+1];
        #pragma unroll
        for (int np = 0; np < 4; np++) {
            float lA0, lB0, lA1, lB1;
            up2(acc[0][np], lA0, lB0);
            up2(acc[1][np], lA1, lB1);
            lA0 = fmaxf(lA0, 0.f); lB0 = fmaxf(lB0, 0.f);
            lA1 = fmaxf(lA1, 0.f); lB1 = fmaxf(lB1, 0.f);
            float pA0 = fmaf(lA1, w30b, lA0*w30a);
            float pA1 = fmaf(lA1, w31b, lA0*w31a);
            float pB0 = fmaf(lB1, w30b, lB0*w30a);
            float pB1 = fmaf(lB1, w31b, lB0*w31a);
            #pragma unroll
            for (int off = 16; off; off >>= 1) {
                pA0 += __shfl_xor_sync(0xffffffffu, pA0, off);
                pA1 += __shfl_xor_sync(0xffffffffu, pA1, off);
                pB0 += __shfl_xor_sync(0xffffffffu, pB0, off);
                pB1 += __shfl_xor_sync(0xffffffffu, pB1, off);
            }
            if (lane == 0) {
                int nA = nc + 2*np, nB = nA + 1;
                sPart[ch*64 + nA*2 + 0] = pA0;
                sPart[ch*64 + nA*2 + 1] = pA1;
                sPart[ch*64 + nB*2 + 0] = pB0;
                sPart[ch*64 + nB*2 + 1] = pB1;
            }
        }
    }
    __syncthreads();
    if (t < 64) {
        int n = t >> 1, c = t & 1;
        sEm[n*2 + c] = sPart[n*2 + c] + sPart[64 + n*2 + c] + b3[c];
    }
    __syncthreads();
    // per-node logsumexp over 2x2 factor table
    if (t < 64) {
        int n = t >> 1, c = t & 1;
        float A = sAB[n*2], B = sAB[n*2+1];
        float em0 = sEm[n*2], em1 = sEm[n*2+1];
        float a = (c == 0) ? (A + B + em0) : (-2.f*A + em0);
        float d = (c == 0) ? (-2.f*B + em1) : (A + B + em1);
        float mx = fmaxf(a, d), mn = fminf(a, d);
        sNew[n*2 + c] = mx + log1pf(expf(mn - mx));
    }
    __syncthreads();
    // GRU(h_f2v), x = new[sib]; weights overlay sW
    float* sWih = sW + 12480; float* sbih = sW + 12864; float* sbhh = sW + 13056;
    for (int i4 = t; i4 < 3120; i4 += 256)
        ((float4*)sW)[i4] = ((const float4*)g_WhhF)[i4];
    for (int i4 = t; i4 < 96; i4 += 256) ((float4*)sWih)[i4] = ((const float4*)gWih)[i4];
    if (t < 192) { sbih[t] = gbih[t]; sbhh[t] = gbhh[t]; }
    __syncthreads();
    int nn = t >> 3, s0b = t & 7, sibl = nn ^ 1;
    float x0 = sNew[sibl*2], x1 = sNew[sibl*2 + 1];
    #pragma unroll
    for (int j2 = 0; j2 < 8; j2++) {
        int s = s0b + j2*8;
        float gir = fmaf(x1, sWih[2*s+1],       fmaf(x0, sWih[2*s],       sbih[s]));
        float giz = fmaf(x1, sWih[2*(64+s)+1],  fmaf(x0, sWih[2*(64+s)],  sbih[64+s]));
        float gin = fmaf(x1, sWih[2*(128+s)+1], fmaf(x0, sWih[2*(128+s)], sbih[128+s]));
        float ghr = sbhh[s], ghz = sbhh[64+s], ghn = sbhh[128+s];
        const float* wr = sW + s*65;
        const float* wz = sW + (64+s)*65;
        const float* wg = sW + (128+s)*65;
        #pragma unroll 8
        for (int k = 0; k < 64; k++) {
            float h = sXT[(64+k)*36 + sibl];   // == h_f2v[mb+nn][k]
            ghr = fmaf(h, wr[k], ghr);
            ghz = fmaf(h, wz[k], ghz);
            ghn = fmaf(h, wg[k], ghn);
        }
        float r  = sigm(gir + ghr);
        float z  = sigm(giz + ghz);
        float gg = tanh_fast(fmaf(r, ghn, gin));
        float h  = sXT[(64+s)*36 + sibl];
        g_hf[(mb+nn)*SD + s] = fmaf(z, h - gg, gg);
    }
}

// ---------------- K4: readout MLP + softmax ----------------
// smem floats: sW1 8256 | sW2 16512 | snm 64 | sh1 128 | sh2 128 | sp 8 = 25096
#define K4_SMEM (25096*4)
__global__ void __launch_bounds__(128) k4_readout(
    const float* __restrict__ W1, const float* __restrict__ b1,
    const float* __restrict__ W2, const float* __restrict__ b2,
    const float* __restrict__ W3, const float* __restrict__ b3,
    float* __restrict__ out)
{
    extern __shared__ float sm[];
    float* sW1 = sm;
    float* sW2 = sm + 8256;
    float* snm = sm + 24768;
    float* sh1 = sm + 24832;
    float* sh2 = sm + 24960;
    float* sp  = sm + 25088;
    int t = threadIdx.x, v = blockIdx.x;
    for (int i = t; i < 8192; i += 128)  { int c = i >> 6, k = i & 63;  sW1[k*129+c] = W1[i]; }
    for (int i = t; i < 16384; i += 128) { int c = i >> 7, k = i & 127; sW2[k*129+c] = W2[i]; }
    if (t < 64) {
        float s = 0.f;
        #pragma unroll
        for (int d = 0; d < 8; d++) s += g_hf[g_varlist[v*DEG + d]*SD + t];
        snm[t] = s;
    }
    __syncthreads();
    {
        float acc = b1[t];
        #pragma unroll 8
        for (int k = 0; k < 64; k++) acc = fmaf(snm[k], sW1[k*129 + t], acc);
        sh1[t] = fmaxf(acc, 0.f);
    }
    __syncthreads();
    {
        float acc = b2[t];
        #pragma unroll 8
        for (int k = 0; k < 128; k++) acc = fmaf(sh1[k], sW2[k*129 + t], acc);
        sh2[t] = fmaxf(acc, 0.f);
    }
    __syncthreads();
    float h2 = sh2[t];
    float p0 = h2 * W3[t], p1 = h2 * W3[128 + t];
    #pragma unroll
    for (int off = 16; off; off >>= 1) {
        p0 += __shfl_xor_sync(0xffffffffu, p0, off);
        p1 += __shfl_xor_sync(0xffffffffu, p1, off);
    }
    int wid = t >> 5;
    if ((t & 31) == 0) { sp[wid*2] = p0; sp[wid*2+1] = p1; }
    __syncthreads();
    if (t == 0) {
        float l0 = sp[0] + sp[2] + sp[4] + sp[6] + b3[0];
        float l1 = sp[1] + sp[3] + sp[5] + sp[7] + b3[1];
        float m = fmaxf(l0, l1);
        float e0 = expf(l0 - m), e1 = expf(l1 - m);
        float inv = 1.f / (e0 + e1);
        out[v*2]     = e0 * inv;
        out[v*2 + 1] = e1 * inv;
    }
}

// ---------------- launch ----------------
extern "C" void kernel_launch(void* const* d_in, const int* in_sizes, int n_in,
                              void* d_out, int out_size) {
    (void)in_sizes; (void)n_in; (void)out_size;
    const float* J        = (const float*)d_in[0];
    const float* b        = (const float*)d_in[1];
    const int*   node_var = (const int*)  d_in[2];
    // d_in[3], d_in[4] (e1_row, e1_col) intentionally unused (structure rebuilt on device)
    const float* v2f_W1 = (const float*)d_in[5];
    const float* v2f_b1 = (const float*)d_in[6];
    const float* v2f_W2 = (const float*)d_in[7];
    const float* v2f_b2 = (const float*)d_in[8];
    const float* v2f_W3 = (const float*)d_in[9];
    const float* v2f_b3 = (const float*)d_in[10];
    const float* f2v_W1 = (const float*)d_in[11];
    const float* f2v_b1 = (const float*)d_in[12];
    const float* f2v_W2 = (const float*)d_in[13];
    const float* f2v_b2 = (const float*)d_in[14];
    const float* f2v_W3 = (const float*)d_in[15];
    const float* f2v_b3 = (const float*)d_in[16];
    const float* gv_Wih = (const float*)d_in[17];
    const float* gv_Whh = (const float*)d_in[18];
    const float* gv_bih = (const float*)d_in[19];
    const float* gv_bhh = (const float*)d_in[20];
    const float* gf_Wih = (const float*)d_in[21];
    const float* gf_Whh = (const float*)d_in[22];
    const float* gf_bih = (const float*)d_in[23];
    const float* gf_bhh = (const float*)d_in[24];
    const float* ro_W1  = (const float*)d_in[25];
    const float* ro_b1  = (const float*)d_in[26];
    const float* ro_W2  = (const float*)d_in[27];
    const float* ro_b2  = (const float*)d_in[28];
    const float* ro_W3  = (const float*)d_in[29];
    const float* ro_b3  = (const float*)d_in[30];

    cudaFuncSetAttribute((const void*)k2_edges,   cudaFuncAttributeMaxDynamicSharedMemorySize, K2_SMEM);
    cudaFuncSetAttribute((const void*)k3_f2v,     cudaFuncAttributeMaxDynamicSharedMemorySize, K3_SMEM);
    cudaFuncSetAttribute((const void*)k4_readout, cudaFuncAttributeMaxDynamicSharedMemorySize, K4_SMEM);

    k_init_a<<<2048, 256>>>();
    k_init_bc<<<1, 1024>>>(node_var);
    k_prep<<<65, 256>>>(v2f_W1, v2f_W2, f2v_W1, f2v_W2, gv_Whh, gf_Whh);
    for (int s = 0; s < NSTEPS; s++) {
        k2_edges<<<NV, 256, K2_SMEM>>>(v2f_b1, v2f_b2, v2f_W3, v2f_b3,
                                       gv_Wih, gv_bih, gv_bhh, b);
        k3_f2v<<<NM/32, 256, K3_SMEM>>>(J, f2v_b1, f2v_b2, f2v_W3, f2v_b3,
                                        gf_Wih, gf_bih, gf_bhh, b, node_var);
    }
    k4_readout<<<NV, 128, K4_SMEM>>>(ro_W1, ro_b1, ro_W2, ro_b2, ro_W3, ro_b3, (float*)d_out);
}